// round 3
// baseline (speedup 1.0000x reference)
#include <cuda_runtime.h>
#include <math.h>

#define NN 50000
#define NE 800000
#define IN_DIM 64
#define HID 128
#define NLAYERS 4

// Persistent scratch (no allocations allowed)
__device__ float g_h[NN * HID];      // node embeddings
__device__ float g_msum[NN * HID];   // neighbor-sum accumulator
__device__ float g_deg[NN];          // in-degree

// ---------------------------------------------------------------------------
__global__ void __launch_bounds__(256) zero_deg_kernel() {
    int i = blockIdx.x * blockDim.x + threadIdx.x;
    if (i < NN) g_deg[i] = 0.0f;
}

__global__ void __launch_bounds__(256) deg_kernel(const int* __restrict__ dst) {
    int e = blockIdx.x * blockDim.x + threadIdx.x;
    if (e < NE) atomicAdd(&g_deg[dst[e]], 1.0f);
}

__global__ void __launch_bounds__(256) zero_msum_kernel() {
    int i = blockIdx.x * blockDim.x + threadIdx.x;
    if (i < NN * HID) g_msum[i] = 0.0f;
}

// warp per edge: gather h[src] row (float4), scatter-add into msum[dst]
__global__ void __launch_bounds__(256) scatter_kernel(const int* __restrict__ src,
                                                      const int* __restrict__ dst) {
    int t = blockIdx.x * blockDim.x + threadIdx.x;
    int e = t >> 5;
    int lane = t & 31;
    if (e >= NE) return;
    int s = src[e];
    int d = dst[e];
    const float4 v = *reinterpret_cast<const float4*>(&g_h[s * HID + lane * 4]);
    float* m = &g_msum[d * HID + lane * 4];
    atomicAdd(m + 0, v.x);
    atomicAdd(m + 1, v.y);
    atomicAdd(m + 2, v.z);
    atomicAdd(m + 3, v.w);
}

// ---------------------------------------------------------------------------
// h = x @ W_embed + b   (M=50000, K=64, N=128), 32-row tiles, 256 threads
__global__ void __launch_bounds__(256) embed_kernel(const float* __restrict__ x,
                                                    const float* __restrict__ W,
                                                    const float* __restrict__ b) {
    __shared__ float A_s[32][IN_DIM];
    __shared__ float B_s[IN_DIM][HID];
    int tid = threadIdx.x;
    int tx = tid & 15, ty = tid >> 4;
    int row0 = blockIdx.x * 32;

#pragma unroll
    for (int i = 0; i < 8; i++) {
        int idx = tid + i * 256;
        int r = idx >> 6, k = idx & 63;
        int row = row0 + r;
        A_s[r][k] = (row < NN) ? x[row * IN_DIM + k] : 0.0f;
    }
#pragma unroll
    for (int i = 0; i < 32; i++) {
        int idx = tid + i * 256;
        B_s[idx >> 7][idx & 127] = W[idx];
    }
    __syncthreads();

    float acc[2][8];
#pragma unroll
    for (int rr = 0; rr < 2; rr++)
#pragma unroll
        for (int j = 0; j < 8; j++) acc[rr][j] = 0.0f;

#pragma unroll 8
    for (int k = 0; k < IN_DIM; k++) {
        float a0 = A_s[2 * ty][k];
        float a1 = A_s[2 * ty + 1][k];
        float4 bv0 = *reinterpret_cast<const float4*>(&B_s[k][tx * 8]);
        float4 bv1 = *reinterpret_cast<const float4*>(&B_s[k][tx * 8 + 4]);
        acc[0][0] += a0 * bv0.x; acc[0][1] += a0 * bv0.y;
        acc[0][2] += a0 * bv0.z; acc[0][3] += a0 * bv0.w;
        acc[0][4] += a0 * bv1.x; acc[0][5] += a0 * bv1.y;
        acc[0][6] += a0 * bv1.z; acc[0][7] += a0 * bv1.w;
        acc[1][0] += a1 * bv0.x; acc[1][1] += a1 * bv0.y;
        acc[1][2] += a1 * bv0.z; acc[1][3] += a1 * bv0.w;
        acc[1][4] += a1 * bv1.x; acc[1][5] += a1 * bv1.y;
        acc[1][6] += a1 * bv1.z; acc[1][7] += a1 * bv1.w;
    }

#pragma unroll
    for (int rr = 0; rr < 2; rr++) {
        int row = row0 + 2 * ty + rr;
        if (row < NN) {
#pragma unroll
            for (int j = 0; j < 8; j++)
                g_h[row * HID + tx * 8 + j] = acc[rr][j] + b[tx * 8 + j];
        }
    }
}

// ---------------------------------------------------------------------------
// bundle = concat(h, msum/deg) @ W_l + b_l ; L2-normalize ; relu ; h += out
__global__ void __launch_bounds__(256) node_apply_kernel(const float* __restrict__ Wc,
                                                         const float* __restrict__ bc,
                                                         int layer) {
    __shared__ float A_s[32][32];
    __shared__ float B_s[32][HID];
    __shared__ float invdeg_s[32];
    const float* W = Wc + layer * (2 * HID) * HID;
    const float* b = bc + layer * HID;
    int tid = threadIdx.x;
    int tx = tid & 15, ty = tid >> 4;
    int row0 = blockIdx.x * 32;

    if (tid < 32) {
        int row = row0 + tid;
        invdeg_s[tid] = (row < NN) ? 1.0f / fmaxf(g_deg[row], 1.0f) : 0.0f;
    }
    __syncthreads();

    float acc[2][8];
#pragma unroll
    for (int rr = 0; rr < 2; rr++)
#pragma unroll
        for (int j = 0; j < 8; j++) acc[rr][j] = 0.0f;

    for (int kk = 0; kk < 2 * HID; kk += 32) {
#pragma unroll
        for (int i = 0; i < 4; i++) {
            int idx = tid + i * 256;
            int r = idx >> 5, k = idx & 31;
            int gk = kk + k;
            int row = row0 + r;
            float v = 0.0f;
            if (row < NN) {
                if (gk < HID) v = g_h[row * HID + gk];
                else          v = g_msum[row * HID + (gk - HID)] * invdeg_s[r];
            }
            A_s[r][k] = v;
        }
#pragma unroll
        for (int i = 0; i < 16; i++) {
            int idx = tid + i * 256;
            int k = idx >> 7, c = idx & 127;
            B_s[k][c] = W[(kk + k) * HID + c];
        }
        __syncthreads();
#pragma unroll
        for (int k = 0; k < 32; k++) {
            float a0 = A_s[2 * ty][k];
            float a1 = A_s[2 * ty + 1][k];
            float4 bv0 = *reinterpret_cast<const float4*>(&B_s[k][tx * 8]);
            float4 bv1 = *reinterpret_cast<const float4*>(&B_s[k][tx * 8 + 4]);
            acc[0][0] += a0 * bv0.x; acc[0][1] += a0 * bv0.y;
            acc[0][2] += a0 * bv0.z; acc[0][3] += a0 * bv0.w;
            acc[0][4] += a0 * bv1.x; acc[0][5] += a0 * bv1.y;
            acc[0][6] += a0 * bv1.z; acc[0][7] += a0 * bv1.w;
            acc[1][0] += a1 * bv0.x; acc[1][1] += a1 * bv0.y;
            acc[1][2] += a1 * bv0.z; acc[1][3] += a1 * bv0.w;
            acc[1][4] += a1 * bv1.x; acc[1][5] += a1 * bv1.y;
            acc[1][6] += a1 * bv1.z; acc[1][7] += a1 * bv1.w;
        }
        __syncthreads();
    }

    float bias[8];
#pragma unroll
    for (int j = 0; j < 8; j++) bias[j] = b[tx * 8 + j];

#pragma unroll
    for (int rr = 0; rr < 2; rr++) {
        int row = row0 + 2 * ty + rr;
        float v[8];
        float ss = 0.0f;
#pragma unroll
        for (int j = 0; j < 8; j++) {
            v[j] = acc[rr][j] + bias[j];
            ss += v[j] * v[j];
        }
        // reduce across the 16 tx-lanes that share this row
#pragma unroll
        for (int off = 8; off >= 1; off >>= 1)
            ss += __shfl_xor_sync(0xffffffffu, ss, off);
        float inv = 1.0f / fmaxf(sqrtf(ss), 1e-12f);
        if (row < NN) {
#pragma unroll
            for (int j = 0; j < 8; j++) {
                float o = fmaxf(v[j] * inv, 0.0f);
                g_h[row * HID + tx * 8 + j] += o;
            }
        }
    }
}

// ---------------------------------------------------------------------------
// Fused edge readout: concat(h[src],h[dst]) @ W0 relu @ W1 relu @ W2
// 32 edges per block, 256 threads.
__global__ void __launch_bounds__(256) edge_mlp_kernel(
        const int* __restrict__ src, const int* __restrict__ dst,
        const float* __restrict__ W0, const float* __restrict__ b0,
        const float* __restrict__ W1, const float* __restrict__ b1,
        const float* __restrict__ W2, const float* __restrict__ b2,
        float* __restrict__ out) {
    __shared__ float A_s[32][32];
    __shared__ float B_s[32][HID];     // reused as [64][64] in stage 2
    __shared__ float e1_s[32][HID];
    __shared__ float e2_s[32][64];
    __shared__ int src_s[32], dst_s[32];
    __shared__ float W2_s[64 * 2];

    int tid = threadIdx.x;
    int tx = tid & 15, ty = tid >> 4;
    int e0 = blockIdx.x * 32;

    if (tid < 32) { src_s[tid] = src[e0 + tid]; dst_s[tid] = dst[e0 + tid]; }
    if (tid < 128) W2_s[tid] = W2[tid];
    __syncthreads();

    // ---- stage 1: [32,256] @ [256,128] ----
    float acc[2][8];
#pragma unroll
    for (int rr = 0; rr < 2; rr++)
#pragma unroll
        for (int j = 0; j < 8; j++) acc[rr][j] = 0.0f;

    for (int kk = 0; kk < 2 * HID; kk += 32) {
#pragma unroll
        for (int i = 0; i < 4; i++) {
            int idx = tid + i * 256;
            int r = idx >> 5, k = idx & 31;
            int gk = kk + k;
            int node = (gk < HID) ? src_s[r] : dst_s[r];
            int col = gk & (HID - 1);
            A_s[r][k] = g_h[node * HID + col];
        }
#pragma unroll
        for (int i = 0; i < 16; i++) {
            int idx = tid + i * 256;
            int k = idx >> 7, c = idx & 127;
            B_s[k][c] = W0[(kk + k) * HID + c];
        }
        __syncthreads();
#pragma unroll
        for (int k = 0; k < 32; k++) {
            float a0 = A_s[2 * ty][k];
            float a1 = A_s[2 * ty + 1][k];
            float4 bv0 = *reinterpret_cast<const float4*>(&B_s[k][tx * 8]);
            float4 bv1 = *reinterpret_cast<const float4*>(&B_s[k][tx * 8 + 4]);
            acc[0][0] += a0 * bv0.x; acc[0][1] += a0 * bv0.y;
            acc[0][2] += a0 * bv0.z; acc[0][3] += a0 * bv0.w;
            acc[0][4] += a0 * bv1.x; acc[0][5] += a0 * bv1.y;
            acc[0][6] += a0 * bv1.z; acc[0][7] += a0 * bv1.w;
            acc[1][0] += a1 * bv0.x; acc[1][1] += a1 * bv0.y;
            acc[1][2] += a1 * bv0.z; acc[1][3] += a1 * bv0.w;
            acc[1][4] += a1 * bv1.x; acc[1][5] += a1 * bv1.y;
            acc[1][6] += a1 * bv1.z; acc[1][7] += a1 * bv1.w;
        }
        __syncthreads();
    }
#pragma unroll
    for (int rr = 0; rr < 2; rr++)
#pragma unroll
        for (int j = 0; j < 8; j++)
            e1_s[2 * ty + rr][tx * 8 + j] = fmaxf(acc[rr][j] + b0[tx * 8 + j], 0.0f);
    __syncthreads();

    // ---- stage 2: [32,128] @ [128,64] ----
    float acc2[2][4];
#pragma unroll
    for (int rr = 0; rr < 2; rr++)
#pragma unroll
        for (int j = 0; j < 4; j++) acc2[rr][j] = 0.0f;

    float* Bp = &B_s[0][0];
    for (int kk = 0; kk < HID; kk += 64) {
#pragma unroll
        for (int i = 0; i < 16; i++) {
            int idx = tid + i * 256;          // 4096 elements = [64][64]
            int k = idx >> 6, c = idx & 63;
            Bp[idx] = W1[(kk + k) * 64 + c];
        }
        __syncthreads();
#pragma unroll
        for (int k = 0; k < 64; k++) {
            float a0 = e1_s[2 * ty][kk + k];
            float a1 = e1_s[2 * ty + 1][kk + k];
            float4 bv = *reinterpret_cast<const float4*>(&Bp[k * 64 + tx * 4]);
            acc2[0][0] += a0 * bv.x; acc2[0][1] += a0 * bv.y;
            acc2[0][2] += a0 * bv.z; acc2[0][3] += a0 * bv.w;
            acc2[1][0] += a1 * bv.x; acc2[1][1] += a1 * bv.y;
            acc2[1][2] += a1 * bv.z; acc2[1][3] += a1 * bv.w;
        }
        __syncthreads();
    }
#pragma unroll
    for (int rr = 0; rr < 2; rr++)
#pragma unroll
        for (int j = 0; j < 4; j++)
            e2_s[2 * ty + rr][tx * 4 + j] = fmaxf(acc2[rr][j] + b1[tx * 4 + j], 0.0f);
    __syncthreads();

    // ---- stage 3: [32,64] @ [64,2] ----
    if (tid < 64) {
        int r = tid >> 1, c = tid & 1;
        float s = b2[c];
#pragma unroll
        for (int k = 0; k < 64; k++) s += e2_s[r][k] * W2_s[k * 2 + c];
        out[(e0 + r) * 2 + c] = s;
    }
}

// ---------------------------------------------------------------------------
extern "C" void kernel_launch(void* const* d_in, const int* in_sizes, int n_in,
                              void* d_out, int out_size) {
    const float* x       = (const float*)d_in[0];
    const int*   src     = (const int*)d_in[1];
    const int*   dst     = (const int*)d_in[2];
    // d_in[3] snorm_n, d_in[4] snorm_e: all-ones, unused
    const float* W_embed = (const float*)d_in[5];
    const float* b_embed = (const float*)d_in[6];
    const float* W_conv  = (const float*)d_in[7];
    const float* b_conv  = (const float*)d_in[8];
    const float* W0      = (const float*)d_in[9];
    const float* b0      = (const float*)d_in[10];
    const float* W1      = (const float*)d_in[11];
    const float* b1      = (const float*)d_in[12];
    const float* W2      = (const float*)d_in[13];
    const float* b2      = (const float*)d_in[14];
    float* out = (float*)d_out;

    zero_deg_kernel<<<(NN + 255) / 256, 256>>>();
    deg_kernel<<<(NE + 255) / 256, 256>>>(dst);
    embed_kernel<<<(NN + 31) / 32, 256>>>(x, W_embed, b_embed);

    for (int l = 0; l < NLAYERS; l++) {
        zero_msum_kernel<<<(NN * HID + 255) / 256, 256>>>();
        scatter_kernel<<<(NE * 32 + 255) / 256, 256>>>(src, dst);
        node_apply_kernel<<<(NN + 31) / 32, 256>>>(W_conv, b_conv, l);
    }

    edge_mlp_kernel<<<NE / 32, 256>>>(src, dst, W0, b0, W1, b1, W2, b2, out);
}